// round 13
// baseline (speedup 1.0000x reference)
#include <cuda_runtime.h>
#include <cuda_fp16.h>
#include <mma.h>
#include <math.h>

using namespace nvcuda;

#define HDIM   128
#define NMAX   100000
#define EMAX   1000000
#define CDIM   16
#define SCAN_B 1024

// Scratch (static device globals — allocation-free per harness rules)
__device__ float  g_dinv[NMAX];
__device__ __half g_lin [(size_t)NMAX * HDIM];  // lin' = dinv[row]*(act(A)@W), fp16
__device__ __half g_aggh[(size_t)NMAX * HDIM];  // fp16: x, then relu(h) per layer
__device__ __half g_Wh  [3][128 * 128];         // fp16 weights
__device__ float  g_P   [(size_t)NMAX * 32];    // per-node [P_src(16) | P_dst(16)]
__device__ __half g_Q   [(size_t)EMAX * CDIM];  // per-edge eattr @ We (fp16)
__device__ int    g_cnt[NMAX];
__device__ int    g_rowptr[NMAX + 1];
__device__ int    g_cursor[NMAX];
__device__ int    g_csrsrc[EMAX];
__device__ int    g_blocksum[128];
__device__ int    g_blockoff[128];

// ---------------------------------------------------------------- fused prologue:
// blocks [0,bx): x -> fp16 g_aggh; [bx,bx+48): W1..W3 -> fp16; rest: cnt_zero.
__global__ void k_prologue(const float* __restrict__ x,
                           const float* __restrict__ W1,
                           const float* __restrict__ W2,
                           const float* __restrict__ W3,
                           int n, int bx) {
    int b = blockIdx.x, tid = threadIdx.x;
    if (b < bx) {
        int i = b * 256 + tid;
        if (i < n * 32) {
            float4 v = ((const float4*)x)[i];
            __half2 h0 = __floats2half2_rn(v.x, v.y);
            __half2 h1 = __floats2half2_rn(v.z, v.w);
            uint2 o;
            o.x = *(unsigned int*)&h0;
            o.y = *(unsigned int*)&h1;
            ((uint2*)g_aggh)[i] = o;
        }
    } else if (b < bx + 48) {
        int off = b - bx;                 // 0..47, 16 blocks per weight
        int w   = off >> 4;
        int i   = (off & 15) * 256 + tid; // 0..4095 float4
        const float* W = (w == 0) ? W1 : (w == 1) ? W2 : W3;
        float4 v = ((const float4*)W)[i];
        __half2 h0 = __floats2half2_rn(v.x, v.y);
        __half2 h1 = __floats2half2_rn(v.z, v.w);
        uint2 o;
        o.x = *(unsigned int*)&h0;
        o.y = *(unsigned int*)&h1;
        ((uint2*)g_Wh[w])[i] = o;
    } else {
        int i = (b - bx - 48) * 256 + tid;
        if (i < n) g_cnt[i] = 0;
    }
}

// ---------------------------------------------------------------- CSR scans
__global__ void k_scan1(int n) {
    __shared__ int sm[SCAN_B];
    int i = blockIdx.x * SCAN_B + threadIdx.x;
    int v = (i < n) ? g_cnt[i] : 0;
    if (i < n) g_dinv[i] = rsqrtf((float)v + 1.0f);   // +1 self-loop
    sm[threadIdx.x] = v;
    __syncthreads();
    #pragma unroll
    for (int off = 1; off < SCAN_B; off <<= 1) {
        int t = (threadIdx.x >= off) ? sm[threadIdx.x - off] : 0;
        __syncthreads();
        sm[threadIdx.x] += t;
        __syncthreads();
    }
    if (i < n) g_rowptr[i] = sm[threadIdx.x] - v;     // exclusive
    if (threadIdx.x == SCAN_B - 1) g_blocksum[blockIdx.x] = sm[SCAN_B - 1];
}
__global__ void k_scan2(int nb) {
    __shared__ int sm[128];
    int t = threadIdx.x;
    int v = (t < nb) ? g_blocksum[t] : 0;
    sm[t] = v;
    __syncthreads();
    #pragma unroll
    for (int off = 1; off < 128; off <<= 1) {
        int x = (t >= off) ? sm[t - off] : 0;
        __syncthreads();
        sm[t] += x;
        __syncthreads();
    }
    if (t < nb) g_blockoff[t] = sm[t] - v;            // exclusive
}
__global__ void k_scan3(int n, int e) {
    int i = blockIdx.x * SCAN_B + threadIdx.x;
    if (i < n) {
        int r = g_rowptr[i] + g_blockoff[blockIdx.x];
        g_rowptr[i] = r;
        g_cursor[i] = r;
    }
    if (i == 0) g_rowptr[n] = e;
}
__global__ void k_fill(const int* __restrict__ src, const int* __restrict__ dst, int e) {
    int i = blockIdx.x * blockDim.x + threadIdx.x;
    if (i < e) {
        int pos = atomicAdd(&g_cursor[dst[i]], 1);
        g_csrsrc[pos] = src[i];
    }
}

// ---------------------------------------------------------------- GEMM (tensor cores): lin' = fp16( dinv * (g_aggh @ Wh) )
#define GW_LDA  136
#define GW_SMEM (2 * 128 * GW_LDA * 2)   // 69632 B (also covers 64KB fp32 staging)
__global__ void k_gemm_wmma(const __half* __restrict__ Wh, int M, int widx) {
    extern __shared__ char smraw[];
    __half* As = (__half*)smraw;                         // 128 x 136
    __half* Ws = (__half*)(smraw + 128 * GW_LDA * 2);    // 128 x 136

    int tid = threadIdx.x;
    int row0 = blockIdx.x * 128;

    const uint4* W4 = (const uint4*)(g_Wh[widx]);
    #pragma unroll
    for (int i = 0; i < 8; i++) {
        int idx = tid + i * 256;
        int r = idx >> 4, c = (idx & 15) * 8;
        *(uint4*)(Ws + r * GW_LDA + c) = W4[idx];
    }
    const uint4* A4 = (const uint4*)g_aggh;
    #pragma unroll
    for (int i = 0; i < 8; i++) {
        int idx = tid + i * 256;
        int r = idx >> 4, c = (idx & 15) * 8;
        uint4 v = make_uint4(0u, 0u, 0u, 0u);
        if (row0 + r < M) v = A4[(size_t)(row0 + r) * 16 + (idx & 15)];
        *(uint4*)(As + r * GW_LDA + c) = v;
    }
    __syncthreads();

    int warp = tid >> 5;

    wmma::fragment<wmma::accumulator, 16, 16, 16, float> acc[8];
    #pragma unroll
    for (int c = 0; c < 8; c++) wmma::fill_fragment(acc[c], 0.f);

    #pragma unroll
    for (int k = 0; k < 8; k++) {
        wmma::fragment<wmma::matrix_a, 16, 16, 16, __half, wmma::row_major> af;
        wmma::load_matrix_sync(af, As + warp * 16 * GW_LDA + k * 16, GW_LDA);
        #pragma unroll
        for (int c = 0; c < 8; c++) {
            wmma::fragment<wmma::matrix_b, 16, 16, 16, __half, wmma::row_major> bf;
            wmma::load_matrix_sync(bf, Ws + k * 16 * GW_LDA + c * 16, GW_LDA);
            wmma::mma_sync(acc[c], af, bf, acc[c]);
        }
    }
    __syncthreads();     // done reading As/Ws — reuse as fp32 staging

    float* Os = (float*)smraw;   // 128 x 128 fp32 (64 KB)
    #pragma unroll
    for (int c = 0; c < 8; c++)
        wmma::store_matrix_sync(Os + warp * 16 * 128 + c * 16, acc[c], 128, wmma::mem_row_major);
    __syncthreads();

    uint2* O2 = (uint2*)g_lin;
    #pragma unroll
    for (int i = 0; i < 16; i++) {
        int idx = tid + i * 256;            // 0..4095 over 128 rows x 32 float4
        int r = idx >> 5, c4 = idx & 31;
        int row = row0 + r;
        if (row < M) {
            float4 v = ((const float4*)Os)[idx];
            float dv = g_dinv[row];
            __half2 h0 = __floats2half2_rn(v.x * dv, v.y * dv);
            __half2 h1 = __floats2half2_rn(v.z * dv, v.w * dv);
            uint2 o;
            o.x = *(unsigned int*)&h0;
            o.y = *(unsigned int*)&h1;
            O2[(size_t)row * 32 + c4] = o;
        }
    }
}

// ---------------------------------------------------------------- aggregate: h[d] = b + dinv[d]*(lin'[d] + sum lin'[s])
// WARP PER NODE: 2 rows per warp instruction (half=lane>>4 selects row,
// c=lane&15 selects 16B chunk). No cross-node divergence; combine via shfl.
__device__ __forceinline__ void hacc4(__half2& a0, __half2& a1, __half2& a2, __half2& a3, uint4 r) {
    a0 = __hadd2(a0, *(__half2*)&r.x);
    a1 = __hadd2(a1, *(__half2*)&r.y);
    a2 = __hadd2(a2, *(__half2*)&r.z);
    a3 = __hadd2(a3, *(__half2*)&r.w);
}
__global__ void k_aggregate(const float* __restrict__ b, int n) {
    int node = (blockIdx.x * blockDim.x + threadIdx.x) >> 5;
    if (node >= n) return;
    int lane = threadIdx.x & 31;
    int half = lane >> 4;      // which row of the pair
    int c    = lane & 15;      // 16B chunk within row

    const uint4* lin4 = (const uint4*)g_lin;   // 16 uint4 per row

    __half2 a0 = __floats2half2_rn(0.f, 0.f);
    __half2 a1 = a0, a2 = a0, a3 = a0;

    int beg = g_rowptr[node];
    int end = g_rowptr[node + 1];

    // first pair: half0 = self row, half1 = first neighbor (if any)
    {
        int idx = (half == 0) ? node : (beg < end ? g_csrsrc[beg] : -1);
        if (idx >= 0) hacc4(a0, a1, a2, a3, lin4[(size_t)idx * 16 + c]);
    }
    int j = beg + 1;

    // main loop: 8 rows per unrolled step (4 pairs), each lane loads own index
    for (; j + 8 <= end; j += 8) {
        int i0 = g_csrsrc[j     + half];
        int i1 = g_csrsrc[j + 2 + half];
        int i2 = g_csrsrc[j + 4 + half];
        int i3 = g_csrsrc[j + 6 + half];
        uint4 r0 = lin4[(size_t)i0 * 16 + c];
        uint4 r1 = lin4[(size_t)i1 * 16 + c];
        uint4 r2 = lin4[(size_t)i2 * 16 + c];
        uint4 r3 = lin4[(size_t)i3 * 16 + c];
        hacc4(a0, a1, a2, a3, r0);
        hacc4(a0, a1, a2, a3, r1);
        hacc4(a0, a1, a2, a3, r2);
        hacc4(a0, a1, a2, a3, r3);
    }
    // tail: pairs (predicated)
    for (; j < end; j += 2) {
        int jj = j + half;
        if (jj < end) {
            int idx = g_csrsrc[jj];
            hacc4(a0, a1, a2, a3, lin4[(size_t)idx * 16 + c]);
        }
    }

    // combine the two halves (xor 16)
    unsigned m = 0xffffffffu;
    a0 = __hadd2(a0, __shfl_xor_sync(m, a0, 16));
    a1 = __hadd2(a1, __shfl_xor_sync(m, a1, 16));
    a2 = __hadd2(a2, __shfl_xor_sync(m, a2, 16));
    a3 = __hadd2(a3, __shfl_xor_sync(m, a3, 16));

    if (half == 0) {
        float2 f0 = __half22float2(a0);
        float2 f1 = __half22float2(a1);
        float2 f2 = __half22float2(a2);
        float2 f3 = __half22float2(a3);

        float di = g_dinv[node];
        const float4* b4 = (const float4*)b;
        float4 bb0 = b4[c * 2];
        float4 bb1 = b4[c * 2 + 1];

        __half2 h0 = __floats2half2_rn(fmaxf(fmaf(f0.x, di, bb0.x), 0.f),
                                       fmaxf(fmaf(f0.y, di, bb0.y), 0.f));
        __half2 h1 = __floats2half2_rn(fmaxf(fmaf(f1.x, di, bb0.z), 0.f),
                                       fmaxf(fmaf(f1.y, di, bb0.w), 0.f));
        __half2 h2 = __floats2half2_rn(fmaxf(fmaf(f2.x, di, bb1.x), 0.f),
                                       fmaxf(fmaf(f2.y, di, bb1.y), 0.f));
        __half2 h3 = __floats2half2_rn(fmaxf(fmaf(f3.x, di, bb1.z), 0.f),
                                       fmaxf(fmaf(f3.y, di, bb1.w), 0.f));
        uint4 oh;
        oh.x = *(unsigned int*)&h0;
        oh.y = *(unsigned int*)&h1;
        oh.z = *(unsigned int*)&h2;
        oh.w = *(unsigned int*)&h3;
        ((uint4*)g_aggh)[(size_t)node * 16 + c] = oh;
    }
}

// ---------------------------------------------------------------- node projection:
// P[n, 32] = g_aggh[n,128] @ Wp[128,32]  (g_aggh already = relu(h3), fp16)
#define PROJ_BM 64
__global__ void k_proj(const float* __restrict__ Wfc, int n) {
    __shared__ float Ws[128 * 32];        // Ws[k*32 + l]
    __shared__ float As[PROJ_BM * 128];   // 32 KB

    int tid = threadIdx.x;
    for (int idx = tid; idx < 128 * 32; idx += 256) {
        int k = idx >> 5, l = idx & 31;
        Ws[idx] = (l < 16) ? Wfc[k * 16 + l] : Wfc[(128 + k) * 16 + (l - 16)];
    }

    int row0 = blockIdx.x * PROJ_BM;
    const uint4* A4 = (const uint4*)g_aggh;   // 16 uint4 per row
    #pragma unroll
    for (int i = 0; i < 4; i++) {
        int idx = tid + i * 256;              // 0..1023 over 64 rows x 16 chunks
        int r = idx >> 4, c = idx & 15;
        uint4 v = make_uint4(0u, 0u, 0u, 0u);
        if (row0 + r < n) v = A4[(size_t)(row0 + r) * 16 + c];
        __half2 h0 = *(__half2*)&v.x;
        __half2 h1 = *(__half2*)&v.y;
        __half2 h2 = *(__half2*)&v.z;
        __half2 h3 = *(__half2*)&v.w;
        float2 f0 = __half22float2(h0);
        float2 f1 = __half22float2(h1);
        float2 f2 = __half22float2(h2);
        float2 f3 = __half22float2(h3);
        float* dstp = As + r * 128 + c * 8;
        dstp[0] = f0.x; dstp[1] = f0.y; dstp[2] = f1.x; dstp[3] = f1.y;
        dstp[4] = f2.x; dstp[5] = f2.y; dstp[6] = f3.x; dstp[7] = f3.y;
    }
    __syncthreads();

    int warp = tid >> 5, lane = tid & 31;
    int rbase = warp * 8;
    float4* As4 = (float4*)As;

    float acc[8];
    #pragma unroll
    for (int r = 0; r < 8; r++) acc[r] = 0.f;

    #pragma unroll 4
    for (int k4 = 0; k4 < 32; k4++) {
        float w0 = Ws[(k4 * 4 + 0) * 32 + lane];
        float w1 = Ws[(k4 * 4 + 1) * 32 + lane];
        float w2 = Ws[(k4 * 4 + 2) * 32 + lane];
        float w3 = Ws[(k4 * 4 + 3) * 32 + lane];
        #pragma unroll
        for (int r = 0; r < 8; r++) {
            float4 a = As4[(rbase + r) * 32 + k4];
            acc[r] = fmaf(a.x, w0, acc[r]);
            acc[r] = fmaf(a.y, w1, acc[r]);
            acc[r] = fmaf(a.z, w2, acc[r]);
            acc[r] = fmaf(a.w, w3, acc[r]);
        }
    }

    #pragma unroll
    for (int r = 0; r < 8; r++) {
        int row = row0 + rbase + r;
        if (row < n) g_P[(size_t)row * 32 + lane] = acc[r];
    }
}

// ---------------------------------------------------------------- Q = eattr @ We (wmma) + fused degree histogram
#define QG_LDA 40
__global__ void k_qgemm(const float* __restrict__ eattr, const float* __restrict__ Wfc,
                        const int* __restrict__ dst, int e) {
    __shared__ __half eaS[128 * QG_LDA];   // 10240 B
    __shared__ __half WeS[32 * 16];        // 1024 B
    __shared__ float  QS [128 * 16];       // 8192 B

    int tid = threadIdx.x;
    int e0 = blockIdx.x * 128;

    // fused histogram (cnt zeroed by prologue; this kernel runs after it)
    if (tid < 128 && e0 + tid < e)
        atomicAdd(&g_cnt[dst[e0 + tid]], 1);

    if (tid < 256) {                        // 512 halves, 2 per thread
        WeS[tid]       = __float2half(Wfc[256 * 16 + tid]);
        WeS[tid + 256] = __float2half(Wfc[256 * 16 + tid + 256]);
    }
    const float4* ea4 = (const float4*)eattr;
    #pragma unroll
    for (int i = 0; i < 4; i++) {
        int idx = tid + i * 256;            // 0..1023
        int r = idx >> 3, c = idx & 7;      // row, float4-chunk
        float4 v = make_float4(0.f, 0.f, 0.f, 0.f);
        if (e0 + r < e) v = ea4[(size_t)(e0 + r) * 8 + c];
        __half2 h0 = __floats2half2_rn(v.x, v.y);
        __half2 h1 = __floats2half2_rn(v.z, v.w);
        uint2 o;
        o.x = *(unsigned int*)&h0;
        o.y = *(unsigned int*)&h1;
        *(uint2*)(eaS + r * QG_LDA + c * 4) = o;
    }
    __syncthreads();

    int warp = tid >> 5;
    wmma::fragment<wmma::accumulator, 16, 16, 16, float> acc;
    wmma::fill_fragment(acc, 0.f);
    #pragma unroll
    for (int k = 0; k < 2; k++) {
        wmma::fragment<wmma::matrix_a, 16, 16, 16, __half, wmma::row_major> af;
        wmma::fragment<wmma::matrix_b, 16, 16, 16, __half, wmma::row_major> bf;
        wmma::load_matrix_sync(af, eaS + warp * 16 * QG_LDA + k * 16, QG_LDA);
        wmma::load_matrix_sync(bf, WeS + k * 16 * 16, 16);
        wmma::mma_sync(acc, af, bf, acc);
    }
    wmma::store_matrix_sync(QS + warp * 16 * 16, acc, 16, wmma::mem_row_major);
    __syncthreads();

    int r = tid >> 1, half = tid & 1;
    if (e0 + r < e) {
        const float* srcq = QS + r * 16 + half * 8;
        __half2 h0 = __floats2half2_rn(srcq[0], srcq[1]);
        __half2 h1 = __floats2half2_rn(srcq[2], srcq[3]);
        __half2 h2 = __floats2half2_rn(srcq[4], srcq[5]);
        __half2 h3 = __floats2half2_rn(srcq[6], srcq[7]);
        uint4 o;
        o.x = *(unsigned int*)&h0;
        o.y = *(unsigned int*)&h1;
        o.z = *(unsigned int*)&h2;
        o.w = *(unsigned int*)&h3;
        *(uint4*)(g_Q + (size_t)(e0 + r) * 16 + half * 8) = o;
    }
}

// ---------------------------------------------------------------- edge output: out = logsoftmax(P_src[s] + P_dst[d] + Q[e] + b)
#define EB 16   // edges per block (256 threads = 16 edges x 16 classes)
__global__ void k_edge3(const int* __restrict__ src, const int* __restrict__ dst,
                        const float* __restrict__ bfc, float* __restrict__ out, int e) {
    __shared__ float bs[CDIM];
    int tid = threadIdx.x;
    if (tid < CDIM) bs[tid] = bfc[tid];
    __syncthreads();

    int el = tid >> 4, c = tid & 15;
    int edge = blockIdx.x * EB + el;
    bool valid = edge < e;
    int ce = valid ? edge : e - 1;

    int s = src[ce], d = dst[ce];
    float q = __half2float(g_Q[(size_t)ce * 16 + c]);
    float acc = bs[c] + q + g_P[(size_t)s * 32 + c] + g_P[(size_t)d * 32 + 16 + c];

    float m = acc;
    #pragma unroll
    for (int off = 8; off; off >>= 1)
        m = fmaxf(m, __shfl_xor_sync(0xffffffffu, m, off));
    float ex = __expf(acc - m);
    float ss = ex;
    #pragma unroll
    for (int off = 8; off; off >>= 1)
        ss += __shfl_xor_sync(0xffffffffu, ss, off);
    float res = acc - m - __logf(ss);
    if (valid) out[(size_t)edge * CDIM + c] = res;
}

// ---------------------------------------------------------------- launch
extern "C" void kernel_launch(void* const* d_in, const int* in_sizes, int n_in,
                              void* d_out, int out_size) {
    const float* x     = (const float*)d_in[0];
    const int*   ei    = (const int*)  d_in[1];
    const float* eattr = (const float*)d_in[2];
    const float* W1 = (const float*)d_in[3];  const float* b1 = (const float*)d_in[4];
    const float* W2 = (const float*)d_in[5];  const float* b2 = (const float*)d_in[6];
    const float* W3 = (const float*)d_in[7];  const float* b3 = (const float*)d_in[8];
    const float* Wfc = (const float*)d_in[9]; const float* bfc = (const float*)d_in[10];
    float* out = (float*)d_out;

    int n = in_sizes[0] / HDIM;
    int e = in_sizes[1] / 2;
    const int* src = ei;
    const int* dst = ei + e;

    cudaFuncSetAttribute(k_gemm_wmma, cudaFuncAttributeMaxDynamicSharedMemorySize, GW_SMEM);

    int bx   = (n * 32 + 255) / 256;          // x-convert blocks
    int bc   = (n + 255) / 256;               // cnt_zero blocks
    int be   = (e + 255) / 256;
    int bgem = (n + 127) / 128;
    int bagg = (int)(((long long)n * 32 + 255) / 256);   // warp per node
    int bedg = (e + EB - 1) / EB;
    int bqg  = (e + 127) / 128;
    int nscan = (n + SCAN_B - 1) / SCAN_B;

    // ---- fused prologue: x/W fp16 converts + cnt_zero
    k_prologue<<<bx + 48 + bc, 256>>>(x, W1, W2, W3, n, bx);

    // ---- Q GEMM + fused degree histogram
    k_qgemm<<<bqg, 256>>>(eattr, Wfc, dst, e);

    // ---- CSR scans + fill
    k_scan1<<<nscan, SCAN_B>>>(n);
    k_scan2<<<1, 128>>>(nscan);
    k_scan3<<<nscan, SCAN_B>>>(n, e);
    k_fill <<<be, 256>>>(src, dst, e);

    // ---- 3 GCN layers
    k_gemm_wmma<<<bgem, 256, GW_SMEM>>>(nullptr, n, 0);
    k_aggregate<<<bagg, 256>>>(b1, n);

    k_gemm_wmma<<<bgem, 256, GW_SMEM>>>(nullptr, n, 1);
    k_aggregate<<<bagg, 256>>>(b2, n);

    k_gemm_wmma<<<bgem, 256, GW_SMEM>>>(nullptr, n, 2);
    k_aggregate<<<bagg, 256>>>(b3, n);

    // ---- factored edge classifier
    k_proj <<<(n + PROJ_BM - 1) / PROJ_BM, 256>>>(Wfc, n);
    k_edge3<<<bedg, 256>>>(src, dst, bfc, out, e);
}

// round 14
// speedup vs baseline: 1.0187x; 1.0187x over previous
#include <cuda_runtime.h>
#include <cuda_fp16.h>
#include <mma.h>
#include <math.h>

using namespace nvcuda;

#define HDIM   128
#define NMAX   100000
#define EMAX   1000000
#define CDIM   16

// Scratch (static device globals — allocation-free per harness rules)
__device__ float  g_dinv[NMAX];
__device__ __half g_lin [(size_t)NMAX * HDIM];  // lin' = dinv[row]*(act(A)@W), fp16
__device__ __half g_aggh[(size_t)NMAX * HDIM];  // fp16: x, then relu(h) per layer
__device__ __half g_Wh  [3][128 * 128];         // fp16 weights
__device__ float  g_P   [(size_t)NMAX * 32];    // per-node [P_src(16) | P_dst(16)]
__device__ __half g_Q   [(size_t)EMAX * CDIM];  // per-edge eattr @ We (fp16)
__device__ int    g_cnt[NMAX];
__device__ int    g_start[NMAX];                // CSR segment start (unordered alloc)
__device__ int    g_cursor[NMAX];
__device__ int    g_csrsrc[EMAX];
__device__ int    g_total;                      // segment allocator counter

// ---------------------------------------------------------------- fused prologue:
// blocks [0,bx): x -> fp16 g_aggh; [bx,bx+48): W1..W3 -> fp16; rest: cnt_zero (+g_total).
__global__ void k_prologue(const float* __restrict__ x,
                           const float* __restrict__ W1,
                           const float* __restrict__ W2,
                           const float* __restrict__ W3,
                           int n, int bx) {
    int b = blockIdx.x, tid = threadIdx.x;
    if (b < bx) {
        int i = b * 256 + tid;
        if (i < n * 32) {
            float4 v = ((const float4*)x)[i];
            __half2 h0 = __floats2half2_rn(v.x, v.y);
            __half2 h1 = __floats2half2_rn(v.z, v.w);
            uint2 o;
            o.x = *(unsigned int*)&h0;
            o.y = *(unsigned int*)&h1;
            ((uint2*)g_aggh)[i] = o;
        }
    } else if (b < bx + 48) {
        int off = b - bx;                 // 0..47, 16 blocks per weight
        int w   = off >> 4;
        int i   = (off & 15) * 256 + tid; // 0..4095 float4
        const float* W = (w == 0) ? W1 : (w == 1) ? W2 : W3;
        float4 v = ((const float4*)W)[i];
        __half2 h0 = __floats2half2_rn(v.x, v.y);
        __half2 h1 = __floats2half2_rn(v.z, v.w);
        uint2 o;
        o.x = *(unsigned int*)&h0;
        o.y = *(unsigned int*)&h1;
        ((uint2*)g_Wh[w])[i] = o;
    } else {
        int i = (b - bx - 48) * 256 + tid;
        if (i < n) g_cnt[i] = 0;
        if (i == 0) g_total = 0;          // allocator reset (graph-replay safe)
    }
}

// ---------------------------------------------------------------- CSR segment allocation (replaces 3 scan kernels)
// Order-free: warp-scan counts, one atomicAdd per warp on g_total.
__global__ void k_alloc(int n) {
    int i = blockIdx.x * blockDim.x + threadIdx.x;
    int lane = threadIdx.x & 31;
    unsigned m = 0xffffffffu;

    int v = (i < n) ? g_cnt[i] : 0;
    if (i < n) g_dinv[i] = rsqrtf((float)v + 1.0f);   // +1 self-loop

    // warp inclusive scan
    int s = v;
    #pragma unroll
    for (int off = 1; off < 32; off <<= 1) {
        int t = __shfl_up_sync(m, s, off);
        if (lane >= off) s += t;
    }
    int wtotal = __shfl_sync(m, s, 31);
    int base = 0;
    if (lane == 31 && wtotal > 0) base = atomicAdd(&g_total, wtotal);
    base = __shfl_sync(m, base, 31);

    if (i < n) {
        int start = base + s - v;         // exclusive within warp
        g_start[i]  = start;
        g_cursor[i] = start;
    }
}
__global__ void k_fill(const int* __restrict__ src, const int* __restrict__ dst, int e) {
    int i = blockIdx.x * blockDim.x + threadIdx.x;
    if (i < e) {
        int pos = atomicAdd(&g_cursor[dst[i]], 1);
        g_csrsrc[pos] = src[i];
    }
}

// ---------------------------------------------------------------- GEMM (tensor cores): lin' = fp16( dinv * (g_aggh @ Wh) )
#define GW_LDA  136
#define GW_SMEM (2 * 128 * GW_LDA * 2)   // 69632 B (also covers 64KB fp32 staging)
__global__ void k_gemm_wmma(const __half* __restrict__ Wh, int M, int widx) {
    extern __shared__ char smraw[];
    __half* As = (__half*)smraw;                         // 128 x 136
    __half* Ws = (__half*)(smraw + 128 * GW_LDA * 2);    // 128 x 136

    int tid = threadIdx.x;
    int row0 = blockIdx.x * 128;

    const uint4* W4 = (const uint4*)(g_Wh[widx]);
    #pragma unroll
    for (int i = 0; i < 8; i++) {
        int idx = tid + i * 256;
        int r = idx >> 4, c = (idx & 15) * 8;
        *(uint4*)(Ws + r * GW_LDA + c) = W4[idx];
    }
    const uint4* A4 = (const uint4*)g_aggh;
    #pragma unroll
    for (int i = 0; i < 8; i++) {
        int idx = tid + i * 256;
        int r = idx >> 4, c = (idx & 15) * 8;
        uint4 v = make_uint4(0u, 0u, 0u, 0u);
        if (row0 + r < M) v = A4[(size_t)(row0 + r) * 16 + (idx & 15)];
        *(uint4*)(As + r * GW_LDA + c) = v;
    }
    __syncthreads();

    int warp = tid >> 5;

    wmma::fragment<wmma::accumulator, 16, 16, 16, float> acc[8];
    #pragma unroll
    for (int c = 0; c < 8; c++) wmma::fill_fragment(acc[c], 0.f);

    #pragma unroll
    for (int k = 0; k < 8; k++) {
        wmma::fragment<wmma::matrix_a, 16, 16, 16, __half, wmma::row_major> af;
        wmma::load_matrix_sync(af, As + warp * 16 * GW_LDA + k * 16, GW_LDA);
        #pragma unroll
        for (int c = 0; c < 8; c++) {
            wmma::fragment<wmma::matrix_b, 16, 16, 16, __half, wmma::row_major> bf;
            wmma::load_matrix_sync(bf, Ws + k * 16 * GW_LDA + c * 16, GW_LDA);
            wmma::mma_sync(acc[c], af, bf, acc[c]);
        }
    }
    __syncthreads();     // done reading As/Ws — reuse as fp32 staging

    float* Os = (float*)smraw;   // 128 x 128 fp32 (64 KB)
    #pragma unroll
    for (int c = 0; c < 8; c++)
        wmma::store_matrix_sync(Os + warp * 16 * 128 + c * 16, acc[c], 128, wmma::mem_row_major);
    __syncthreads();

    uint2* O2 = (uint2*)g_lin;
    #pragma unroll
    for (int i = 0; i < 16; i++) {
        int idx = tid + i * 256;            // 0..4095 over 128 rows x 32 float4
        int r = idx >> 5, c4 = idx & 31;
        int row = row0 + r;
        if (row < M) {
            float4 v = ((const float4*)Os)[idx];
            float dv = g_dinv[row];
            __half2 h0 = __floats2half2_rn(v.x * dv, v.y * dv);
            __half2 h1 = __floats2half2_rn(v.z * dv, v.w * dv);
            uint2 o;
            o.x = *(unsigned int*)&h0;
            o.y = *(unsigned int*)&h1;
            O2[(size_t)row * 32 + c4] = o;
        }
    }
}

// ---------------------------------------------------------------- aggregate: h[d] = b + dinv[d]*(lin'[d] + sum lin'[s])
// R12 layout (fastest measured): 16-lane group per node, fp16 packed accumulation.
__global__ void k_aggregate(const float* __restrict__ b, int n) {
    int grp  = (blockIdx.x * blockDim.x + threadIdx.x) >> 4;   // node id
    int lane = threadIdx.x & 15;                               // 16B chunk
    if (grp >= n) return;

    const uint4* lin4 = (const uint4*)g_lin;   // row stride = 16 uint4

    uint4 self = lin4[(size_t)grp * 16 + lane];
    __half2 a0 = *(__half2*)&self.x;
    __half2 a1 = *(__half2*)&self.y;
    __half2 a2 = *(__half2*)&self.z;
    __half2 a3 = *(__half2*)&self.w;

    int beg = g_start[grp];
    int end = beg + g_cnt[grp];
    int j = beg;
    for (; j + 8 <= end; j += 8) {
        int s0 = g_csrsrc[j];
        int s1 = g_csrsrc[j + 1];
        int s2 = g_csrsrc[j + 2];
        int s3 = g_csrsrc[j + 3];
        int s4 = g_csrsrc[j + 4];
        int s5 = g_csrsrc[j + 5];
        int s6 = g_csrsrc[j + 6];
        int s7 = g_csrsrc[j + 7];
        uint4 r0 = lin4[(size_t)s0 * 16 + lane];
        uint4 r1 = lin4[(size_t)s1 * 16 + lane];
        uint4 r2 = lin4[(size_t)s2 * 16 + lane];
        uint4 r3 = lin4[(size_t)s3 * 16 + lane];
        uint4 r4 = lin4[(size_t)s4 * 16 + lane];
        uint4 r5 = lin4[(size_t)s5 * 16 + lane];
        uint4 r6 = lin4[(size_t)s6 * 16 + lane];
        uint4 r7 = lin4[(size_t)s7 * 16 + lane];
        a0 = __hadd2(a0, *(__half2*)&r0.x); a1 = __hadd2(a1, *(__half2*)&r0.y);
        a2 = __hadd2(a2, *(__half2*)&r0.z); a3 = __hadd2(a3, *(__half2*)&r0.w);
        a0 = __hadd2(a0, *(__half2*)&r1.x); a1 = __hadd2(a1, *(__half2*)&r1.y);
        a2 = __hadd2(a2, *(__half2*)&r1.z); a3 = __hadd2(a3, *(__half2*)&r1.w);
        a0 = __hadd2(a0, *(__half2*)&r2.x); a1 = __hadd2(a1, *(__half2*)&r2.y);
        a2 = __hadd2(a2, *(__half2*)&r2.z); a3 = __hadd2(a3, *(__half2*)&r2.w);
        a0 = __hadd2(a0, *(__half2*)&r3.x); a1 = __hadd2(a1, *(__half2*)&r3.y);
        a2 = __hadd2(a2, *(__half2*)&r3.z); a3 = __hadd2(a3, *(__half2*)&r3.w);
        a0 = __hadd2(a0, *(__half2*)&r4.x); a1 = __hadd2(a1, *(__half2*)&r4.y);
        a2 = __hadd2(a2, *(__half2*)&r4.z); a3 = __hadd2(a3, *(__half2*)&r4.w);
        a0 = __hadd2(a0, *(__half2*)&r5.x); a1 = __hadd2(a1, *(__half2*)&r5.y);
        a2 = __hadd2(a2, *(__half2*)&r5.z); a3 = __hadd2(a3, *(__half2*)&r5.w);
        a0 = __hadd2(a0, *(__half2*)&r6.x); a1 = __hadd2(a1, *(__half2*)&r6.y);
        a2 = __hadd2(a2, *(__half2*)&r6.z); a3 = __hadd2(a3, *(__half2*)&r6.w);
        a0 = __hadd2(a0, *(__half2*)&r7.x); a1 = __hadd2(a1, *(__half2*)&r7.y);
        a2 = __hadd2(a2, *(__half2*)&r7.z); a3 = __hadd2(a3, *(__half2*)&r7.w);
    }
    for (; j < end; j++) {
        int s = g_csrsrc[j];
        uint4 r = lin4[(size_t)s * 16 + lane];
        a0 = __hadd2(a0, *(__half2*)&r.x); a1 = __hadd2(a1, *(__half2*)&r.y);
        a2 = __hadd2(a2, *(__half2*)&r.z); a3 = __hadd2(a3, *(__half2*)&r.w);
    }

    float2 f0 = __half22float2(a0);
    float2 f1 = __half22float2(a1);
    float2 f2 = __half22float2(a2);
    float2 f3 = __half22float2(a3);

    float di = g_dinv[grp];
    const float4* b4 = (const float4*)b;
    float4 bb0 = b4[lane * 2];
    float4 bb1 = b4[lane * 2 + 1];

    // relu(h) packed straight to fp16 (no fp32 store)
    __half2 h0 = __floats2half2_rn(fmaxf(fmaf(f0.x, di, bb0.x), 0.f),
                                   fmaxf(fmaf(f0.y, di, bb0.y), 0.f));
    __half2 h1 = __floats2half2_rn(fmaxf(fmaf(f1.x, di, bb0.z), 0.f),
                                   fmaxf(fmaf(f1.y, di, bb0.w), 0.f));
    __half2 h2 = __floats2half2_rn(fmaxf(fmaf(f2.x, di, bb1.x), 0.f),
                                   fmaxf(fmaf(f2.y, di, bb1.y), 0.f));
    __half2 h3 = __floats2half2_rn(fmaxf(fmaf(f3.x, di, bb1.z), 0.f),
                                   fmaxf(fmaf(f3.y, di, bb1.w), 0.f));
    uint4 oh;
    oh.x = *(unsigned int*)&h0;
    oh.y = *(unsigned int*)&h1;
    oh.z = *(unsigned int*)&h2;
    oh.w = *(unsigned int*)&h3;
    ((uint4*)g_aggh)[(size_t)grp * 16 + lane] = oh;
}

// ---------------------------------------------------------------- node projection:
// P[n, 32] = g_aggh[n,128] @ Wp[128,32]  (g_aggh already = relu(h3), fp16)
#define PROJ_BM 64
__global__ void k_proj(const float* __restrict__ Wfc, int n) {
    __shared__ float Ws[128 * 32];        // Ws[k*32 + l]
    __shared__ float As[PROJ_BM * 128];   // 32 KB

    int tid = threadIdx.x;
    for (int idx = tid; idx < 128 * 32; idx += 256) {
        int k = idx >> 5, l = idx & 31;
        Ws[idx] = (l < 16) ? Wfc[k * 16 + l] : Wfc[(128 + k) * 16 + (l - 16)];
    }

    int row0 = blockIdx.x * PROJ_BM;
    const uint4* A4 = (const uint4*)g_aggh;   // 16 uint4 per row
    #pragma unroll
    for (int i = 0; i < 4; i++) {
        int idx = tid + i * 256;              // 0..1023 over 64 rows x 16 chunks
        int r = idx >> 4, c = idx & 15;
        uint4 v = make_uint4(0u, 0u, 0u, 0u);
        if (row0 + r < n) v = A4[(size_t)(row0 + r) * 16 + c];
        __half2 h0 = *(__half2*)&v.x;
        __half2 h1 = *(__half2*)&v.y;
        __half2 h2 = *(__half2*)&v.z;
        __half2 h3 = *(__half2*)&v.w;
        float2 f0 = __half22float2(h0);
        float2 f1 = __half22float2(h1);
        float2 f2 = __half22float2(h2);
        float2 f3 = __half22float2(h3);
        float* dstp = As + r * 128 + c * 8;
        dstp[0] = f0.x; dstp[1] = f0.y; dstp[2] = f1.x; dstp[3] = f1.y;
        dstp[4] = f2.x; dstp[5] = f2.y; dstp[6] = f3.x; dstp[7] = f3.y;
    }
    __syncthreads();

    int warp = tid >> 5, lane = tid & 31;
    int rbase = warp * 8;
    float4* As4 = (float4*)As;

    float acc[8];
    #pragma unroll
    for (int r = 0; r < 8; r++) acc[r] = 0.f;

    #pragma unroll 4
    for (int k4 = 0; k4 < 32; k4++) {
        float w0 = Ws[(k4 * 4 + 0) * 32 + lane];
        float w1 = Ws[(k4 * 4 + 1) * 32 + lane];
        float w2 = Ws[(k4 * 4 + 2) * 32 + lane];
        float w3 = Ws[(k4 * 4 + 3) * 32 + lane];
        #pragma unroll
        for (int r = 0; r < 8; r++) {
            float4 a = As4[(rbase + r) * 32 + k4];
            acc[r] = fmaf(a.x, w0, acc[r]);
            acc[r] = fmaf(a.y, w1, acc[r]);
            acc[r] = fmaf(a.z, w2, acc[r]);
            acc[r] = fmaf(a.w, w3, acc[r]);
        }
    }

    #pragma unroll
    for (int r = 0; r < 8; r++) {
        int row = row0 + rbase + r;
        if (row < n) g_P[(size_t)row * 32 + lane] = acc[r];
    }
}

// ---------------------------------------------------------------- Q = eattr @ We (wmma) + fused degree histogram
#define QG_LDA 40
__global__ void k_qgemm(const float* __restrict__ eattr, const float* __restrict__ Wfc,
                        const int* __restrict__ dst, int e) {
    __shared__ __half eaS[128 * QG_LDA];   // 10240 B
    __shared__ __half WeS[32 * 16];        // 1024 B
    __shared__ float  QS [128 * 16];       // 8192 B

    int tid = threadIdx.x;
    int e0 = blockIdx.x * 128;

    // fused histogram (cnt zeroed by prologue; this kernel runs after it)
    if (tid < 128 && e0 + tid < e)
        atomicAdd(&g_cnt[dst[e0 + tid]], 1);

    if (tid < 256) {                        // 512 halves, 2 per thread
        WeS[tid]       = __float2half(Wfc[256 * 16 + tid]);
        WeS[tid + 256] = __float2half(Wfc[256 * 16 + tid + 256]);
    }
    const float4* ea4 = (const float4*)eattr;
    #pragma unroll
    for (int i = 0; i < 4; i++) {
        int idx = tid + i * 256;            // 0..1023
        int r = idx >> 3, c = idx & 7;      // row, float4-chunk
        float4 v = make_float4(0.f, 0.f, 0.f, 0.f);
        if (e0 + r < e) v = ea4[(size_t)(e0 + r) * 8 + c];
        __half2 h0 = __floats2half2_rn(v.x, v.y);
        __half2 h1 = __floats2half2_rn(v.z, v.w);
        uint2 o;
        o.x = *(unsigned int*)&h0;
        o.y = *(unsigned int*)&h1;
        *(uint2*)(eaS + r * QG_LDA + c * 4) = o;
    }
    __syncthreads();

    int warp = tid >> 5;
    wmma::fragment<wmma::accumulator, 16, 16, 16, float> acc;
    wmma::fill_fragment(acc, 0.f);
    #pragma unroll
    for (int k = 0; k < 2; k++) {
        wmma::fragment<wmma::matrix_a, 16, 16, 16, __half, wmma::row_major> af;
        wmma::fragment<wmma::matrix_b, 16, 16, 16, __half, wmma::row_major> bf;
        wmma::load_matrix_sync(af, eaS + warp * 16 * QG_LDA + k * 16, QG_LDA);
        wmma::load_matrix_sync(bf, WeS + k * 16 * 16, 16);
        wmma::mma_sync(acc, af, bf, acc);
    }
    wmma::store_matrix_sync(QS + warp * 16 * 16, acc, 16, wmma::mem_row_major);
    __syncthreads();

    int r = tid >> 1, half = tid & 1;
    if (e0 + r < e) {
        const float* srcq = QS + r * 16 + half * 8;
        __half2 h0 = __floats2half2_rn(srcq[0], srcq[1]);
        __half2 h1 = __floats2half2_rn(srcq[2], srcq[3]);
        __half2 h2 = __floats2half2_rn(srcq[4], srcq[5]);
        __half2 h3 = __floats2half2_rn(srcq[6], srcq[7]);
        uint4 o;
        o.x = *(unsigned int*)&h0;
        o.y = *(unsigned int*)&h1;
        o.z = *(unsigned int*)&h2;
        o.w = *(unsigned int*)&h3;
        *(uint4*)(g_Q + (size_t)(e0 + r) * 16 + half * 8) = o;
    }
}

// ---------------------------------------------------------------- edge output: out = logsoftmax(P_src[s] + P_dst[d] + Q[e] + b)
#define EB 16   // edges per block (256 threads = 16 edges x 16 classes)
__global__ void k_edge3(const int* __restrict__ src, const int* __restrict__ dst,
                        const float* __restrict__ bfc, float* __restrict__ out, int e) {
    __shared__ float bs[CDIM];
    int tid = threadIdx.x;
    if (tid < CDIM) bs[tid] = bfc[tid];
    __syncthreads();

    int el = tid >> 4, c = tid & 15;
    int edge = blockIdx.x * EB + el;
    bool valid = edge < e;
    int ce = valid ? edge : e - 1;

    int s = src[ce], d = dst[ce];
    float q = __half2float(g_Q[(size_t)ce * 16 + c]);
    float acc = bs[c] + q + g_P[(size_t)s * 32 + c] + g_P[(size_t)d * 32 + 16 + c];

    float m = acc;
    #pragma unroll
    for (int off = 8; off; off >>= 1)
        m = fmaxf(m, __shfl_xor_sync(0xffffffffu, m, off));
    float ex = __expf(acc - m);
    float ss = ex;
    #pragma unroll
    for (int off = 8; off; off >>= 1)
        ss += __shfl_xor_sync(0xffffffffu, ss, off);
    float res = acc - m - __logf(ss);
    if (valid) out[(size_t)edge * CDIM + c] = res;
}

// ---------------------------------------------------------------- launch
extern "C" void kernel_launch(void* const* d_in, const int* in_sizes, int n_in,
                              void* d_out, int out_size) {
    const float* x     = (const float*)d_in[0];
    const int*   ei    = (const int*)  d_in[1];
    const float* eattr = (const float*)d_in[2];
    const float* W1 = (const float*)d_in[3];  const float* b1 = (const float*)d_in[4];
    const float* W2 = (const float*)d_in[5];  const float* b2 = (const float*)d_in[6];
    const float* W3 = (const float*)d_in[7];  const float* b3 = (const float*)d_in[8];
    const float* Wfc = (const float*)d_in[9]; const float* bfc = (const float*)d_in[10];
    float* out = (float*)d_out;

    int n = in_sizes[0] / HDIM;
    int e = in_sizes[1] / 2;
    const int* src = ei;
    const int* dst = ei + e;

    cudaFuncSetAttribute(k_gemm_wmma, cudaFuncAttributeMaxDynamicSharedMemorySize, GW_SMEM);

    int bx   = (n * 32 + 255) / 256;          // x-convert blocks
    int bc   = (n + 255) / 256;               // cnt_zero blocks
    int be   = (e + 255) / 256;
    int bgem = (n + 127) / 128;
    int bagg = (int)(((long long)n * 16 + 255) / 256);   // 16 lanes per node
    int bedg = (e + EB - 1) / EB;
    int bqg  = (e + 127) / 128;

    // ---- fused prologue: x/W fp16 converts + cnt_zero + allocator reset
    k_prologue<<<bx + 48 + bc, 256>>>(x, W1, W2, W3, n, bx);

    // ---- Q GEMM + fused degree histogram
    k_qgemm<<<bqg, 256>>>(eattr, Wfc, dst, e);

    // ---- CSR segment alloc (1 kernel) + fill
    k_alloc<<<bc, 256>>>(n);
    k_fill <<<be, 256>>>(src, dst, e);

    // ---- 3 GCN layers
    k_gemm_wmma<<<bgem, 256, GW_SMEM>>>(nullptr, n, 0);
    k_aggregate<<<bagg, 256>>>(b1, n);

    k_gemm_wmma<<<bgem, 256, GW_SMEM>>>(nullptr, n, 1);
    k_aggregate<<<bagg, 256>>>(b2, n);

    k_gemm_wmma<<<bgem, 256, GW_SMEM>>>(nullptr, n, 2);
    k_aggregate<<<bagg, 256>>>(b3, n);

    // ---- factored edge classifier
    k_proj <<<(n + PROJ_BM - 1) / PROJ_BM, 256>>>(Wfc, n);
    k_edge3<<<bedg, 256>>>(src, dst, bfc, out, e);
}

// round 15
// speedup vs baseline: 1.0619x; 1.0424x over previous
#include <cuda_runtime.h>
#include <cuda_fp16.h>
#include <mma.h>
#include <math.h>

using namespace nvcuda;

#define HDIM   128
#define NMAX   100000
#define EMAX   1000000
#define CDIM   16

// Scratch (static device globals — allocation-free per harness rules)
__device__ float  g_dinv[NMAX];
__device__ __half g_lin [(size_t)NMAX * HDIM];  // lin' = dinv[row]*(act(A)@W), fp16
__device__ __half g_aggh[(size_t)NMAX * HDIM];  // fp16 relu(h) per layer
__device__ __half g_Wh  [3][128 * 128];         // fp16 weights
__device__ __half g_P   [(size_t)NMAX * 32];    // per-node [P_src(16) | P_dst(16)], fp16
__device__ __half g_Q   [(size_t)EMAX * CDIM];  // per-edge eattr @ We + b (fp16)
__device__ int    g_cnt[NMAX];
__device__ int    g_start[NMAX];                // CSR segment start (unordered alloc)
__device__ int    g_cursor[NMAX];
__device__ int    g_csrsrc[EMAX];
__device__ int    g_total;                      // segment allocator counter

// ---------------------------------------------------------------- fused prologue:
// blocks [0,48): W1..W3 -> fp16; rest: cnt_zero (+g_total reset).
__global__ void k_prologue(const float* __restrict__ W1,
                           const float* __restrict__ W2,
                           const float* __restrict__ W3,
                           int n) {
    int b = blockIdx.x, tid = threadIdx.x;
    if (b < 48) {
        int w = b >> 4;
        int i = (b & 15) * 256 + tid;     // 0..4095 float4
        const float* W = (w == 0) ? W1 : (w == 1) ? W2 : W3;
        float4 v = ((const float4*)W)[i];
        __half2 h0 = __floats2half2_rn(v.x, v.y);
        __half2 h1 = __floats2half2_rn(v.z, v.w);
        uint2 o;
        o.x = *(unsigned int*)&h0;
        o.y = *(unsigned int*)&h1;
        ((uint2*)g_Wh[w])[i] = o;
    } else {
        int i = (b - 48) * 256 + tid;
        if (i < n) g_cnt[i] = 0;
        if (i == 0) g_total = 0;          // allocator reset (graph-replay safe)
    }
}

// ---------------------------------------------------------------- CSR segment allocation
__global__ void k_alloc(int n) {
    int i = blockIdx.x * blockDim.x + threadIdx.x;
    int lane = threadIdx.x & 31;
    unsigned m = 0xffffffffu;

    int v = (i < n) ? g_cnt[i] : 0;
    if (i < n) g_dinv[i] = rsqrtf((float)v + 1.0f);   // +1 self-loop

    int s = v;
    #pragma unroll
    for (int off = 1; off < 32; off <<= 1) {
        int t = __shfl_up_sync(m, s, off);
        if (lane >= off) s += t;
    }
    int wtotal = __shfl_sync(m, s, 31);
    int base = 0;
    if (lane == 31 && wtotal > 0) base = atomicAdd(&g_total, wtotal);
    base = __shfl_sync(m, base, 31);

    if (i < n) {
        int start = base + s - v;
        g_start[i]  = start;
        g_cursor[i] = start;
    }
}
__global__ void k_fill(const int* __restrict__ src, const int* __restrict__ dst, int e) {
    int i = blockIdx.x * blockDim.x + threadIdx.x;
    if (i < e) {
        int pos = atomicAdd(&g_cursor[dst[i]], 1);
        g_csrsrc[pos] = src[i];
    }
}

// ---------------------------------------------------------------- GEMM (tensor cores): lin' = fp16( dinv * (A @ Wh) )
// A source: Af32 (layer 1, fp32 x) or g_aggh (fp16 relu(h)).
#define GW_LDA  136
#define GW_SMEM (2 * 128 * GW_LDA * 2)   // 69632 B (also covers 64KB fp32 staging)
__global__ void k_gemm_wmma(const float* __restrict__ Af32, int M, int widx) {
    extern __shared__ char smraw[];
    __half* As = (__half*)smraw;                         // 128 x 136
    __half* Ws = (__half*)(smraw + 128 * GW_LDA * 2);    // 128 x 136

    int tid = threadIdx.x;
    int row0 = blockIdx.x * 128;

    const uint4* W4 = (const uint4*)(g_Wh[widx]);
    #pragma unroll
    for (int i = 0; i < 8; i++) {
        int idx = tid + i * 256;
        int r = idx >> 4, c = (idx & 15) * 8;
        *(uint4*)(Ws + r * GW_LDA + c) = W4[idx];
    }
    if (Af32) {
        // fp32 input path (layer 1): convert to fp16 while staging
        const float4* Ax = (const float4*)Af32;
        #pragma unroll
        for (int i = 0; i < 8; i++) {
            int idx = tid + i * 256;
            int r = idx >> 4, q = idx & 15;
            uint4 v = make_uint4(0u, 0u, 0u, 0u);
            if (row0 + r < M) {
                float4 f0 = Ax[(size_t)(row0 + r) * 32 + q * 2];
                float4 f1 = Ax[(size_t)(row0 + r) * 32 + q * 2 + 1];
                __half2 h0 = __floats2half2_rn(f0.x, f0.y);
                __half2 h1 = __floats2half2_rn(f0.z, f0.w);
                __half2 h2 = __floats2half2_rn(f1.x, f1.y);
                __half2 h3 = __floats2half2_rn(f1.z, f1.w);
                v.x = *(unsigned int*)&h0;
                v.y = *(unsigned int*)&h1;
                v.z = *(unsigned int*)&h2;
                v.w = *(unsigned int*)&h3;
            }
            *(uint4*)(As + r * GW_LDA + q * 8) = v;
        }
    } else {
        const uint4* A4 = (const uint4*)g_aggh;
        #pragma unroll
        for (int i = 0; i < 8; i++) {
            int idx = tid + i * 256;
            int r = idx >> 4, q = idx & 15;
            uint4 v = make_uint4(0u, 0u, 0u, 0u);
            if (row0 + r < M) v = A4[(size_t)(row0 + r) * 16 + q];
            *(uint4*)(As + r * GW_LDA + q * 8) = v;
        }
    }
    __syncthreads();

    int warp = tid >> 5;

    wmma::fragment<wmma::accumulator, 16, 16, 16, float> acc[8];
    #pragma unroll
    for (int c = 0; c < 8; c++) wmma::fill_fragment(acc[c], 0.f);

    #pragma unroll
    for (int k = 0; k < 8; k++) {
        wmma::fragment<wmma::matrix_a, 16, 16, 16, __half, wmma::row_major> af;
        wmma::load_matrix_sync(af, As + warp * 16 * GW_LDA + k * 16, GW_LDA);
        #pragma unroll
        for (int c = 0; c < 8; c++) {
            wmma::fragment<wmma::matrix_b, 16, 16, 16, __half, wmma::row_major> bf;
            wmma::load_matrix_sync(bf, Ws + k * 16 * GW_LDA + c * 16, GW_LDA);
            wmma::mma_sync(acc[c], af, bf, acc[c]);
        }
    }
    __syncthreads();     // done reading As/Ws — reuse as fp32 staging

    float* Os = (float*)smraw;   // 128 x 128 fp32 (64 KB)
    #pragma unroll
    for (int c = 0; c < 8; c++)
        wmma::store_matrix_sync(Os + warp * 16 * 128 + c * 16, acc[c], 128, wmma::mem_row_major);
    __syncthreads();

    uint2* O2 = (uint2*)g_lin;
    #pragma unroll
    for (int i = 0; i < 16; i++) {
        int idx = tid + i * 256;            // 0..4095 over 128 rows x 32 float4
        int r = idx >> 5, c4 = idx & 31;
        int row = row0 + r;
        if (row < M) {
            float4 v = ((const float4*)Os)[idx];
            float dv = g_dinv[row];
            __half2 h0 = __floats2half2_rn(v.x * dv, v.y * dv);
            __half2 h1 = __floats2half2_rn(v.z * dv, v.w * dv);
            uint2 o;
            o.x = *(unsigned int*)&h0;
            o.y = *(unsigned int*)&h1;
            O2[(size_t)row * 32 + c4] = o;
        }
    }
}

// ---------------------------------------------------------------- aggregate: h[d] = b + dinv[d]*(lin'[d] + sum lin'[s])
// 16-lane group per node, fp16 packed accumulation, L2-only gathers (__ldcg).
__global__ void k_aggregate(const float* __restrict__ b, int n) {
    int grp  = (blockIdx.x * blockDim.x + threadIdx.x) >> 4;   // node id
    int lane = threadIdx.x & 15;                               // 16B chunk
    if (grp >= n) return;

    const uint4* lin4 = (const uint4*)g_lin;   // row stride = 16 uint4

    uint4 self = __ldcg(&lin4[(size_t)grp * 16 + lane]);
    __half2 a0 = *(__half2*)&self.x;
    __half2 a1 = *(__half2*)&self.y;
    __half2 a2 = *(__half2*)&self.z;
    __half2 a3 = *(__half2*)&self.w;

    int beg = g_start[grp];
    int end = beg + g_cnt[grp];
    int j = beg;
    for (; j + 8 <= end; j += 8) {
        int s0 = g_csrsrc[j];
        int s1 = g_csrsrc[j + 1];
        int s2 = g_csrsrc[j + 2];
        int s3 = g_csrsrc[j + 3];
        int s4 = g_csrsrc[j + 4];
        int s5 = g_csrsrc[j + 5];
        int s6 = g_csrsrc[j + 6];
        int s7 = g_csrsrc[j + 7];
        uint4 r0 = __ldcg(&lin4[(size_t)s0 * 16 + lane]);
        uint4 r1 = __ldcg(&lin4[(size_t)s1 * 16 + lane]);
        uint4 r2 = __ldcg(&lin4[(size_t)s2 * 16 + lane]);
        uint4 r3 = __ldcg(&lin4[(size_t)s3 * 16 + lane]);
        uint4 r4 = __ldcg(&lin4[(size_t)s4 * 16 + lane]);
        uint4 r5 = __ldcg(&lin4[(size_t)s5 * 16 + lane]);
        uint4 r6 = __ldcg(&lin4[(size_t)s6 * 16 + lane]);
        uint4 r7 = __ldcg(&lin4[(size_t)s7 * 16 + lane]);
        a0 = __hadd2(a0, *(__half2*)&r0.x); a1 = __hadd2(a1, *(__half2*)&r0.y);
        a2 = __hadd2(a2, *(__half2*)&r0.z); a3 = __hadd2(a3, *(__half2*)&r0.w);
        a0 = __hadd2(a0, *(__half2*)&r1.x); a1 = __hadd2(a1, *(__half2*)&r1.y);
        a2 = __hadd2(a2, *(__half2*)&r1.z); a3 = __hadd2(a3, *(__half2*)&r1.w);
        a0 = __hadd2(a0, *(__half2*)&r2.x); a1 = __hadd2(a1, *(__half2*)&r2.y);
        a2 = __hadd2(a2, *(__half2*)&r2.z); a3 = __hadd2(a3, *(__half2*)&r2.w);
        a0 = __hadd2(a0, *(__half2*)&r3.x); a1 = __hadd2(a1, *(__half2*)&r3.y);
        a2 = __hadd2(a2, *(__half2*)&r3.z); a3 = __hadd2(a3, *(__half2*)&r3.w);
        a0 = __hadd2(a0, *(__half2*)&r4.x); a1 = __hadd2(a1, *(__half2*)&r4.y);
        a2 = __hadd2(a2, *(__half2*)&r4.z); a3 = __hadd2(a3, *(__half2*)&r4.w);
        a0 = __hadd2(a0, *(__half2*)&r5.x); a1 = __hadd2(a1, *(__half2*)&r5.y);
        a2 = __hadd2(a2, *(__half2*)&r5.z); a3 = __hadd2(a3, *(__half2*)&r5.w);
        a0 = __hadd2(a0, *(__half2*)&r6.x); a1 = __hadd2(a1, *(__half2*)&r6.y);
        a2 = __hadd2(a2, *(__half2*)&r6.z); a3 = __hadd2(a3, *(__half2*)&r6.w);
        a0 = __hadd2(a0, *(__half2*)&r7.x); a1 = __hadd2(a1, *(__half2*)&r7.y);
        a2 = __hadd2(a2, *(__half2*)&r7.z); a3 = __hadd2(a3, *(__half2*)&r7.w);
    }
    for (; j < end; j++) {
        int s = g_csrsrc[j];
        uint4 r = __ldcg(&lin4[(size_t)s * 16 + lane]);
        a0 = __hadd2(a0, *(__half2*)&r.x); a1 = __hadd2(a1, *(__half2*)&r.y);
        a2 = __hadd2(a2, *(__half2*)&r.z); a3 = __hadd2(a3, *(__half2*)&r.w);
    }

    float2 f0 = __half22float2(a0);
    float2 f1 = __half22float2(a1);
    float2 f2 = __half22float2(a2);
    float2 f3 = __half22float2(a3);

    float di = g_dinv[grp];
    const float4* b4 = (const float4*)b;
    float4 bb0 = b4[lane * 2];
    float4 bb1 = b4[lane * 2 + 1];

    __half2 h0 = __floats2half2_rn(fmaxf(fmaf(f0.x, di, bb0.x), 0.f),
                                   fmaxf(fmaf(f0.y, di, bb0.y), 0.f));
    __half2 h1 = __floats2half2_rn(fmaxf(fmaf(f1.x, di, bb0.z), 0.f),
                                   fmaxf(fmaf(f1.y, di, bb0.w), 0.f));
    __half2 h2 = __floats2half2_rn(fmaxf(fmaf(f2.x, di, bb1.x), 0.f),
                                   fmaxf(fmaf(f2.y, di, bb1.y), 0.f));
    __half2 h3 = __floats2half2_rn(fmaxf(fmaf(f3.x, di, bb1.z), 0.f),
                                   fmaxf(fmaf(f3.y, di, bb1.w), 0.f));
    uint4 oh;
    oh.x = *(unsigned int*)&h0;
    oh.y = *(unsigned int*)&h1;
    oh.z = *(unsigned int*)&h2;
    oh.w = *(unsigned int*)&h3;
    ((uint4*)g_aggh)[(size_t)grp * 16 + lane] = oh;
}

// ---------------------------------------------------------------- node projection:
// P[n, 32] = g_aggh[n,128] @ Wp[128,32], stored fp16.
#define PROJ_BM 64
__global__ void k_proj(const float* __restrict__ Wfc, int n) {
    __shared__ float Ws[128 * 32];        // Ws[k*32 + l]
    __shared__ float As[PROJ_BM * 128];   // 32 KB

    int tid = threadIdx.x;
    for (int idx = tid; idx < 128 * 32; idx += 256) {
        int k = idx >> 5, l = idx & 31;
        Ws[idx] = (l < 16) ? Wfc[k * 16 + l] : Wfc[(128 + k) * 16 + (l - 16)];
    }

    int row0 = blockIdx.x * PROJ_BM;
    const uint4* A4 = (const uint4*)g_aggh;   // 16 uint4 per row
    #pragma unroll
    for (int i = 0; i < 4; i++) {
        int idx = tid + i * 256;              // 0..1023 over 64 rows x 16 chunks
        int r = idx >> 4, c = idx & 15;
        uint4 v = make_uint4(0u, 0u, 0u, 0u);
        if (row0 + r < n) v = A4[(size_t)(row0 + r) * 16 + c];
        __half2 h0 = *(__half2*)&v.x;
        __half2 h1 = *(__half2*)&v.y;
        __half2 h2 = *(__half2*)&v.z;
        __half2 h3 = *(__half2*)&v.w;
        float2 f0 = __half22float2(h0);
        float2 f1 = __half22float2(h1);
        float2 f2 = __half22float2(h2);
        float2 f3 = __half22float2(h3);
        float* dstp = As + r * 128 + c * 8;
        dstp[0] = f0.x; dstp[1] = f0.y; dstp[2] = f1.x; dstp[3] = f1.y;
        dstp[4] = f2.x; dstp[5] = f2.y; dstp[6] = f3.x; dstp[7] = f3.y;
    }
    __syncthreads();

    int warp = tid >> 5, lane = tid & 31;
    int rbase = warp * 8;
    float4* As4 = (float4*)As;

    float acc[8];
    #pragma unroll
    for (int r = 0; r < 8; r++) acc[r] = 0.f;

    #pragma unroll 4
    for (int k4 = 0; k4 < 32; k4++) {
        float w0 = Ws[(k4 * 4 + 0) * 32 + lane];
        float w1 = Ws[(k4 * 4 + 1) * 32 + lane];
        float w2 = Ws[(k4 * 4 + 2) * 32 + lane];
        float w3 = Ws[(k4 * 4 + 3) * 32 + lane];
        #pragma unroll
        for (int r = 0; r < 8; r++) {
            float4 a = As4[(rbase + r) * 32 + k4];
            acc[r] = fmaf(a.x, w0, acc[r]);
            acc[r] = fmaf(a.y, w1, acc[r]);
            acc[r] = fmaf(a.z, w2, acc[r]);
            acc[r] = fmaf(a.w, w3, acc[r]);
        }
    }

    #pragma unroll
    for (int r = 0; r < 8; r++) {
        int row = row0 + rbase + r;
        if (row < n) g_P[(size_t)row * 32 + lane] = __float2half(acc[r]);
    }
}

// ---------------------------------------------------------------- Q = eattr @ We + b (wmma) + fused degree histogram
#define QG_LDA 40
__global__ void k_qgemm(const float* __restrict__ eattr, const float* __restrict__ Wfc,
                        const float* __restrict__ bfc, const int* __restrict__ dst, int e) {
    __shared__ __half eaS[128 * QG_LDA];   // 10240 B
    __shared__ __half WeS[32 * 16];        // 1024 B
    __shared__ float  QS [128 * 16];       // 8192 B
    __shared__ float  bs [CDIM];

    int tid = threadIdx.x;
    int e0 = blockIdx.x * 128;

    // fused histogram (cnt zeroed by prologue; this kernel runs after it)
    if (tid < 128 && e0 + tid < e)
        atomicAdd(&g_cnt[dst[e0 + tid]], 1);

    if (tid < CDIM) bs[tid] = bfc[tid];
    if (tid < 256) {                        // 512 halves, 2 per thread
        WeS[tid]       = __float2half(Wfc[256 * 16 + tid]);
        WeS[tid + 256] = __float2half(Wfc[256 * 16 + tid + 256]);
    }
    const float4* ea4 = (const float4*)eattr;
    #pragma unroll
    for (int i = 0; i < 4; i++) {
        int idx = tid + i * 256;            // 0..1023
        int r = idx >> 3, c = idx & 7;      // row, float4-chunk
        float4 v = make_float4(0.f, 0.f, 0.f, 0.f);
        if (e0 + r < e) v = ea4[(size_t)(e0 + r) * 8 + c];
        __half2 h0 = __floats2half2_rn(v.x, v.y);
        __half2 h1 = __floats2half2_rn(v.z, v.w);
        uint2 o;
        o.x = *(unsigned int*)&h0;
        o.y = *(unsigned int*)&h1;
        *(uint2*)(eaS + r * QG_LDA + c * 4) = o;
    }
    __syncthreads();

    int warp = tid >> 5;
    wmma::fragment<wmma::accumulator, 16, 16, 16, float> acc;
    wmma::fill_fragment(acc, 0.f);
    #pragma unroll
    for (int k = 0; k < 2; k++) {
        wmma::fragment<wmma::matrix_a, 16, 16, 16, __half, wmma::row_major> af;
        wmma::fragment<wmma::matrix_b, 16, 16, 16, __half, wmma::row_major> bf;
        wmma::load_matrix_sync(af, eaS + warp * 16 * QG_LDA + k * 16, QG_LDA);
        wmma::load_matrix_sync(bf, WeS + k * 16 * 16, 16);
        wmma::mma_sync(acc, af, bf, acc);
    }
    wmma::store_matrix_sync(QS + warp * 16 * 16, acc, 16, wmma::mem_row_major);
    __syncthreads();

    int r = tid >> 1, half = tid & 1;
    if (e0 + r < e) {
        const float* srcq = QS + r * 16 + half * 8;
        const float* bb   = bs + half * 8;
        __half2 h0 = __floats2half2_rn(srcq[0] + bb[0], srcq[1] + bb[1]);
        __half2 h1 = __floats2half2_rn(srcq[2] + bb[2], srcq[3] + bb[3]);
        __half2 h2 = __floats2half2_rn(srcq[4] + bb[4], srcq[5] + bb[5]);
        __half2 h3 = __floats2half2_rn(srcq[6] + bb[6], srcq[7] + bb[7]);
        uint4 o;
        o.x = *(unsigned int*)&h0;
        o.y = *(unsigned int*)&h1;
        o.z = *(unsigned int*)&h2;
        o.w = *(unsigned int*)&h3;
        *(uint4*)(g_Q + (size_t)(e0 + r) * 16 + half * 8) = o;
    }
}

// ---------------------------------------------------------------- edge output: out = logsoftmax(P_src[s] + P_dst[d] + Q[e])
#define EB 16   // edges per block (256 threads = 16 edges x 16 classes)
__global__ void k_edge3(const int* __restrict__ src, const int* __restrict__ dst,
                        float* __restrict__ out, int e) {
    int tid = threadIdx.x;
    int el = tid >> 4, c = tid & 15;
    int edge = blockIdx.x * EB + el;
    bool valid = edge < e;
    int ce = valid ? edge : e - 1;

    int s = src[ce], d = dst[ce];
    float q  = __half2float(g_Q[(size_t)ce * 16 + c]);
    float ps = __half2float(g_P[(size_t)s * 32 + c]);
    float pd = __half2float(g_P[(size_t)d * 32 + 16 + c]);
    float acc = q + ps + pd;

    float m = acc;
    #pragma unroll
    for (int off = 8; off; off >>= 1)
        m = fmaxf(m, __shfl_xor_sync(0xffffffffu, m, off));
    float ex = __expf(acc - m);
    float ss = ex;
    #pragma unroll
    for (int off = 8; off; off >>= 1)
        ss += __shfl_xor_sync(0xffffffffu, ss, off);
    float res = acc - m - __logf(ss);
    if (valid) out[(size_t)edge * CDIM + c] = res;
}

// ---------------------------------------------------------------- launch
extern "C" void kernel_launch(void* const* d_in, const int* in_sizes, int n_in,
                              void* d_out, int out_size) {
    const float* x     = (const float*)d_in[0];
    const int*   ei    = (const int*)  d_in[1];
    const float* eattr = (const float*)d_in[2];
    const float* W1 = (const float*)d_in[3];  const float* b1 = (const float*)d_in[4];
    const float* W2 = (const float*)d_in[5];  const float* b2 = (const float*)d_in[6];
    const float* W3 = (const float*)d_in[7];  const float* b3 = (const float*)d_in[8];
    const float* Wfc = (const float*)d_in[9]; const float* bfc = (const float*)d_in[10];
    float* out = (float*)d_out;

    int n = in_sizes[0] / HDIM;
    int e = in_sizes[1] / 2;
    const int* src = ei;
    const int* dst = ei + e;

    cudaFuncSetAttribute(k_gemm_wmma, cudaFuncAttributeMaxDynamicSharedMemorySize, GW_SMEM);

    int bc   = (n + 255) / 256;
    int be   = (e + 255) / 256;
    int bgem = (n + 127) / 128;
    int bagg = (int)(((long long)n * 16 + 255) / 256);   // 16 lanes per node
    int bedg = (e + EB - 1) / EB;
    int bqg  = (e + 127) / 128;

    // ---- fused prologue: W fp16 converts + cnt_zero + allocator reset
    k_prologue<<<48 + bc, 256>>>(W1, W2, W3, n);

    // ---- Q GEMM (+bias) + fused degree histogram
    k_qgemm<<<bqg, 256>>>(eattr, Wfc, bfc, dst, e);

    // ---- CSR segment alloc + fill
    k_alloc<<<bc, 256>>>(n);
    k_fill <<<be, 256>>>(src, dst, e);

    // ---- 3 GCN layers (layer 1 reads x fp32 directly)
    k_gemm_wmma<<<bgem, 256, GW_SMEM>>>(x, n, 0);
    k_aggregate<<<bagg, 256>>>(b1, n);

    k_gemm_wmma<<<bgem, 256, GW_SMEM>>>(nullptr, n, 1);
    k_aggregate<<<bagg, 256>>>(b2, n);

    k_gemm_wmma<<<bgem, 256, GW_SMEM>>>(nullptr, n, 2);
    k_aggregate<<<bagg, 256>>>(b3, n);

    // ---- factored edge classifier
    k_proj <<<(n + PROJ_BM - 1) / PROJ_BM, 256>>>(Wfc, n);
    k_edge3<<<bedg, 256>>>(src, dst, out, e);
}

// round 17
// speedup vs baseline: 1.0815x; 1.0184x over previous
#include <cuda_runtime.h>
#include <cuda_fp16.h>
#include <mma.h>
#include <math.h>

using namespace nvcuda;

#define HDIM   128
#define NMAX   100000
#define EMAX   1000000
#define CDIM   16

// Scratch (static device globals — allocation-free per harness rules)
__device__ float  g_dinv[NMAX];
__device__ __half g_lin [(size_t)NMAX * HDIM];  // lin' = dinv[row]*(act(A)@W), fp16
__device__ __half g_aggh[(size_t)NMAX * HDIM];  // fp16 relu(h) per layer
__device__ __half g_Wh  [3][128 * 128];         // fp16 weights
__device__ __half g_P   [(size_t)NMAX * 32];    // per-node [P_src(16) | P_dst(16)], fp16
__device__ __half g_Q   [(size_t)EMAX * CDIM];  // per-edge eattr @ We + b (fp16)
__device__ int    g_cnt[NMAX];
__device__ int    g_start[NMAX];                // CSR segment start (unordered alloc)
__device__ int    g_cursor[NMAX];
__device__ int    g_csrsrc[EMAX];
__device__ int    g_total;                      // segment allocator counter

// ---------------------------------------------------------------- fused prologue:
// blocks [0,48): W1..W3 -> fp16; rest: cnt_zero (+g_total reset).
__global__ void k_prologue(const float* __restrict__ W1,
                           const float* __restrict__ W2,
                           const float* __restrict__ W3,
                           int n) {
    int b = blockIdx.x, tid = threadIdx.x;
    if (b < 48) {
        int w = b >> 4;
        int i = (b & 15) * 256 + tid;     // 0..4095 float4
        const float* W = (w == 0) ? W1 : (w == 1) ? W2 : W3;
        float4 v = ((const float4*)W)[i];
        __half2 h0 = __floats2half2_rn(v.x, v.y);
        __half2 h1 = __floats2half2_rn(v.z, v.w);
        uint2 o;
        o.x = *(unsigned int*)&h0;
        o.y = *(unsigned int*)&h1;
        ((uint2*)g_Wh[w])[i] = o;
    } else {
        int i = (b - 48) * 256 + tid;
        if (i < n) g_cnt[i] = 0;
        if (i == 0) g_total = 0;          // allocator reset (graph-replay safe)
    }
}

// ---------------------------------------------------------------- CSR segment allocation
__global__ void k_alloc(int n) {
    int i = blockIdx.x * blockDim.x + threadIdx.x;
    int lane = threadIdx.x & 31;
    unsigned m = 0xffffffffu;

    int v = (i < n) ? g_cnt[i] : 0;
    if (i < n) g_dinv[i] = rsqrtf((float)v + 1.0f);   // +1 self-loop

    int s = v;
    #pragma unroll
    for (int off = 1; off < 32; off <<= 1) {
        int t = __shfl_up_sync(m, s, off);
        if (lane >= off) s += t;
    }
    int wtotal = __shfl_sync(m, s, 31);
    int base = 0;
    if (lane == 31 && wtotal > 0) base = atomicAdd(&g_total, wtotal);
    base = __shfl_sync(m, base, 31);

    if (i < n) {
        int start = base + s - v;
        g_start[i]  = start;
        g_cursor[i] = start;
    }
}
__global__ void k_fill(const int* __restrict__ src, const int* __restrict__ dst, int e) {
    int i = blockIdx.x * blockDim.x + threadIdx.x;
    if (i < e) {
        int pos = atomicAdd(&g_cursor[dst[i]], 1);
        g_csrsrc[pos] = src[i];
    }
}

// ---------------------------------------------------------------- GEMM (tensor cores): lin' = fp16( dinv * (A @ Wh) )
// A source: Af32 (layer 1, fp32 x) or g_aggh (fp16 relu(h)).
#define GW_LDA  136
#define GW_SMEM (2 * 128 * GW_LDA * 2)   // 69632 B (also covers 64KB fp32 staging)
__global__ void k_gemm_wmma(const float* __restrict__ Af32, int M, int widx) {
    extern __shared__ char smraw[];
    __half* As = (__half*)smraw;                         // 128 x 136
    __half* Ws = (__half*)(smraw + 128 * GW_LDA * 2);    // 128 x 136

    int tid = threadIdx.x;
    int row0 = blockIdx.x * 128;

    const uint4* W4 = (const uint4*)(g_Wh[widx]);
    #pragma unroll
    for (int i = 0; i < 8; i++) {
        int idx = tid + i * 256;
        int r = idx >> 4, c = (idx & 15) * 8;
        *(uint4*)(Ws + r * GW_LDA + c) = W4[idx];
    }
    if (Af32) {
        // fp32 input path (layer 1): convert to fp16 while staging
        const float4* Ax = (const float4*)Af32;
        #pragma unroll
        for (int i = 0; i < 8; i++) {
            int idx = tid + i * 256;
            int r = idx >> 4, q = idx & 15;
            uint4 v = make_uint4(0u, 0u, 0u, 0u);
            if (row0 + r < M) {
                float4 f0 = Ax[(size_t)(row0 + r) * 32 + q * 2];
                float4 f1 = Ax[(size_t)(row0 + r) * 32 + q * 2 + 1];
                __half2 h0 = __floats2half2_rn(f0.x, f0.y);
                __half2 h1 = __floats2half2_rn(f0.z, f0.w);
                __half2 h2 = __floats2half2_rn(f1.x, f1.y);
                __half2 h3 = __floats2half2_rn(f1.z, f1.w);
                v.x = *(unsigned int*)&h0;
                v.y = *(unsigned int*)&h1;
                v.z = *(unsigned int*)&h2;
                v.w = *(unsigned int*)&h3;
            }
            *(uint4*)(As + r * GW_LDA + q * 8) = v;
        }
    } else {
        const uint4* A4 = (const uint4*)g_aggh;
        #pragma unroll
        for (int i = 0; i < 8; i++) {
            int idx = tid + i * 256;
            int r = idx >> 4, q = idx & 15;
            uint4 v = make_uint4(0u, 0u, 0u, 0u);
            if (row0 + r < M) v = A4[(size_t)(row0 + r) * 16 + q];
            *(uint4*)(As + r * GW_LDA + q * 8) = v;
        }
    }
    __syncthreads();

    int warp = tid >> 5;

    wmma::fragment<wmma::accumulator, 16, 16, 16, float> acc[8];
    #pragma unroll
    for (int c = 0; c < 8; c++) wmma::fill_fragment(acc[c], 0.f);

    #pragma unroll
    for (int k = 0; k < 8; k++) {
        wmma::fragment<wmma::matrix_a, 16, 16, 16, __half, wmma::row_major> af;
        wmma::load_matrix_sync(af, As + warp * 16 * GW_LDA + k * 16, GW_LDA);
        #pragma unroll
        for (int c = 0; c < 8; c++) {
            wmma::fragment<wmma::matrix_b, 16, 16, 16, __half, wmma::row_major> bf;
            wmma::load_matrix_sync(bf, Ws + k * 16 * GW_LDA + c * 16, GW_LDA);
            wmma::mma_sync(acc[c], af, bf, acc[c]);
        }
    }
    __syncthreads();     // done reading As/Ws — reuse as fp32 staging

    float* Os = (float*)smraw;   // 128 x 128 fp32 (64 KB)
    #pragma unroll
    for (int c = 0; c < 8; c++)
        wmma::store_matrix_sync(Os + warp * 16 * 128 + c * 16, acc[c], 128, wmma::mem_row_major);
    __syncthreads();

    uint2* O2 = (uint2*)g_lin;
    #pragma unroll
    for (int i = 0; i < 16; i++) {
        int idx = tid + i * 256;            // 0..4095 over 128 rows x 32 float4
        int r = idx >> 5, c4 = idx & 31;
        int row = row0 + r;
        if (row < M) {
            float4 v = ((const float4*)Os)[idx];
            float dv = g_dinv[row];
            __half2 h0 = __floats2half2_rn(v.x * dv, v.y * dv);
            __half2 h1 = __floats2half2_rn(v.z * dv, v.w * dv);
            uint2 o;
            o.x = *(unsigned int*)&h0;
            o.y = *(unsigned int*)&h1;
            O2[(size_t)row * 32 + c4] = o;
        }
    }
}

// ---------------------------------------------------------------- aggregate: h[d] = b + dinv[d]*(lin'[d] + sum lin'[s])
// 16-lane group per node, fp16 packed accumulation, L2-only gathers (__ldcg).
__global__ void k_aggregate(const float* __restrict__ b, int n) {
    int grp  = (blockIdx.x * blockDim.x + threadIdx.x) >> 4;   // node id
    int lane = threadIdx.x & 15;                               // 16B chunk
    if (grp >= n) return;

    const uint4* lin4 = (const uint4*)g_lin;   // row stride = 16 uint4

    uint4 self = __ldcg(&lin4[(size_t)grp * 16 + lane]);
    __half2 a0 = *(__half2*)&self.x;
    __half2 a1 = *(__half2*)&self.y;
    __half2 a2 = *(__half2*)&self.z;
    __half2 a3 = *(__half2*)&self.w;

    int beg = g_start[grp];
    int end = beg + g_cnt[grp];
    int j = beg;
    for (; j + 8 <= end; j += 8) {
        int s0 = g_csrsrc[j];
        int s1 = g_csrsrc[j + 1];
        int s2 = g_csrsrc[j + 2];
        int s3 = g_csrsrc[j + 3];
        int s4 = g_csrsrc[j + 4];
        int s5 = g_csrsrc[j + 5];
        int s6 = g_csrsrc[j + 6];
        int s7 = g_csrsrc[j + 7];
        uint4 r0 = __ldcg(&lin4[(size_t)s0 * 16 + lane]);
        uint4 r1 = __ldcg(&lin4[(size_t)s1 * 16 + lane]);
        uint4 r2 = __ldcg(&lin4[(size_t)s2 * 16 + lane]);
        uint4 r3 = __ldcg(&lin4[(size_t)s3 * 16 + lane]);
        uint4 r4 = __ldcg(&lin4[(size_t)s4 * 16 + lane]);
        uint4 r5 = __ldcg(&lin4[(size_t)s5 * 16 + lane]);
        uint4 r6 = __ldcg(&lin4[(size_t)s6 * 16 + lane]);
        uint4 r7 = __ldcg(&lin4[(size_t)s7 * 16 + lane]);
        a0 = __hadd2(a0, *(__half2*)&r0.x); a1 = __hadd2(a1, *(__half2*)&r0.y);
        a2 = __hadd2(a2, *(__half2*)&r0.z); a3 = __hadd2(a3, *(__half2*)&r0.w);
        a0 = __hadd2(a0, *(__half2*)&r1.x); a1 = __hadd2(a1, *(__half2*)&r1.y);
        a2 = __hadd2(a2, *(__half2*)&r1.z); a3 = __hadd2(a3, *(__half2*)&r1.w);
        a0 = __hadd2(a0, *(__half2*)&r2.x); a1 = __hadd2(a1, *(__half2*)&r2.y);
        a2 = __hadd2(a2, *(__half2*)&r2.z); a3 = __hadd2(a3, *(__half2*)&r2.w);
        a0 = __hadd2(a0, *(__half2*)&r3.x); a1 = __hadd2(a1, *(__half2*)&r3.y);
        a2 = __hadd2(a2, *(__half2*)&r3.z); a3 = __hadd2(a3, *(__half2*)&r3.w);
        a0 = __hadd2(a0, *(__half2*)&r4.x); a1 = __hadd2(a1, *(__half2*)&r4.y);
        a2 = __hadd2(a2, *(__half2*)&r4.z); a3 = __hadd2(a3, *(__half2*)&r4.w);
        a0 = __hadd2(a0, *(__half2*)&r5.x); a1 = __hadd2(a1, *(__half2*)&r5.y);
        a2 = __hadd2(a2, *(__half2*)&r5.z); a3 = __hadd2(a3, *(__half2*)&r5.w);
        a0 = __hadd2(a0, *(__half2*)&r6.x); a1 = __hadd2(a1, *(__half2*)&r6.y);
        a2 = __hadd2(a2, *(__half2*)&r6.z); a3 = __hadd2(a3, *(__half2*)&r6.w);
        a0 = __hadd2(a0, *(__half2*)&r7.x); a1 = __hadd2(a1, *(__half2*)&r7.y);
        a2 = __hadd2(a2, *(__half2*)&r7.z); a3 = __hadd2(a3, *(__half2*)&r7.w);
    }
    for (; j < end; j++) {
        int s = g_csrsrc[j];
        uint4 r = __ldcg(&lin4[(size_t)s * 16 + lane]);
        a0 = __hadd2(a0, *(__half2*)&r.x); a1 = __hadd2(a1, *(__half2*)&r.y);
        a2 = __hadd2(a2, *(__half2*)&r.z); a3 = __hadd2(a3, *(__half2*)&r.w);
    }

    float2 f0 = __half22float2(a0);
    float2 f1 = __half22float2(a1);
    float2 f2 = __half22float2(a2);
    float2 f3 = __half22float2(a3);

    float di = g_dinv[grp];
    const float4* b4 = (const float4*)b;
    float4 bb0 = b4[lane * 2];
    float4 bb1 = b4[lane * 2 + 1];

    __half2 h0 = __floats2half2_rn(fmaxf(fmaf(f0.x, di, bb0.x), 0.f),
                                   fmaxf(fmaf(f0.y, di, bb0.y), 0.f));
    __half2 h1 = __floats2half2_rn(fmaxf(fmaf(f1.x, di, bb0.z), 0.f),
                                   fmaxf(fmaf(f1.y, di, bb0.w), 0.f));
    __half2 h2 = __floats2half2_rn(fmaxf(fmaf(f2.x, di, bb1.x), 0.f),
                                   fmaxf(fmaf(f2.y, di, bb1.y), 0.f));
    __half2 h3 = __floats2half2_rn(fmaxf(fmaf(f3.x, di, bb1.z), 0.f),
                                   fmaxf(fmaf(f3.y, di, bb1.w), 0.f));
    uint4 oh;
    oh.x = *(unsigned int*)&h0;
    oh.y = *(unsigned int*)&h1;
    oh.z = *(unsigned int*)&h2;
    oh.w = *(unsigned int*)&h3;
    ((uint4*)g_aggh)[(size_t)grp * 16 + lane] = oh;
}

// ---------------------------------------------------------------- node projection:
// P[n, 32] = g_aggh[n,128] @ Wp[128,32], stored fp16.
#define PROJ_BM 64
__global__ void k_proj(const float* __restrict__ Wfc, int n) {
    __shared__ float Ws[128 * 32];        // Ws[k*32 + l]
    __shared__ float As[PROJ_BM * 128];   // 32 KB

    int tid = threadIdx.x;
    for (int idx = tid; idx < 128 * 32; idx += 256) {
        int k = idx >> 5, l = idx & 31;
        Ws[idx] = (l < 16) ? Wfc[k * 16 + l] : Wfc[(128 + k) * 16 + (l - 16)];
    }

    int row0 = blockIdx.x * PROJ_BM;
    const uint4* A4 = (const uint4*)g_aggh;   // 16 uint4 per row
    #pragma unroll
    for (int i = 0; i < 4; i++) {
        int idx = tid + i * 256;              // 0..1023 over 64 rows x 16 chunks
        int r = idx >> 4, c = idx & 15;
        uint4 v = make_uint4(0u, 0u, 0u, 0u);
        if (row0 + r < n) v = A4[(size_t)(row0 + r) * 16 + c];
        __half2 h0 = *(__half2*)&v.x;
        __half2 h1 = *(__half2*)&v.y;
        __half2 h2 = *(__half2*)&v.z;
        __half2 h3 = *(__half2*)&v.w;
        float2 f0 = __half22float2(h0);
        float2 f1 = __half22float2(h1);
        float2 f2 = __half22float2(h2);
        float2 f3 = __half22float2(h3);
        float* dstp = As + r * 128 + c * 8;
        dstp[0] = f0.x; dstp[1] = f0.y; dstp[2] = f1.x; dstp[3] = f1.y;
        dstp[4] = f2.x; dstp[5] = f2.y; dstp[6] = f3.x; dstp[7] = f3.y;
    }
    __syncthreads();

    int warp = tid >> 5, lane = tid & 31;
    int rbase = warp * 8;
    float4* As4 = (float4*)As;

    float acc[8];
    #pragma unroll
    for (int r = 0; r < 8; r++) acc[r] = 0.f;

    #pragma unroll 4
    for (int k4 = 0; k4 < 32; k4++) {
        float w0 = Ws[(k4 * 4 + 0) * 32 + lane];
        float w1 = Ws[(k4 * 4 + 1) * 32 + lane];
        float w2 = Ws[(k4 * 4 + 2) * 32 + lane];
        float w3 = Ws[(k4 * 4 + 3) * 32 + lane];
        #pragma unroll
        for (int r = 0; r < 8; r++) {
            float4 a = As4[(rbase + r) * 32 + k4];
            acc[r] = fmaf(a.x, w0, acc[r]);
            acc[r] = fmaf(a.y, w1, acc[r]);
            acc[r] = fmaf(a.z, w2, acc[r]);
            acc[r] = fmaf(a.w, w3, acc[r]);
        }
    }

    #pragma unroll
    for (int r = 0; r < 8; r++) {
        int row = row0 + rbase + r;
        if (row < n) g_P[(size_t)row * 32 + lane] = __float2half(acc[r]);
    }
}

// ---------------------------------------------------------------- Q = eattr @ We + b (wmma) + fused degree histogram
#define QG_LDA 40
__global__ void k_qgemm(const float* __restrict__ eattr, const float* __restrict__ Wfc,
                        const float* __restrict__ bfc, const int* __restrict__ dst, int e) {
    __shared__ __half eaS[128 * QG_LDA];   // 10240 B
    __shared__ __half WeS[32 * 16];        // 1024 B
    __shared__ float  QS [128 * 16];       // 8192 B
    __shared__ float  bs [CDIM];

    int tid = threadIdx.x;
    int e0 = blockIdx.x * 128;

    // fused histogram (cnt zeroed by prologue; this kernel runs after it)
    if (tid < 128 && e0 + tid < e)
        atomicAdd(&g_cnt[dst[e0 + tid]], 1);

    if (tid < CDIM) bs[tid] = bfc[tid];
    if (tid < 256) {                        // 512 halves, 2 per thread
        WeS[tid]       = __float2half(Wfc[256 * 16 + tid]);
        WeS[tid + 256] = __float2half(Wfc[256 * 16 + tid + 256]);
    }
    const float4* ea4 = (const float4*)eattr;
    #pragma unroll
    for (int i = 0; i < 4; i++) {
        int idx = tid + i * 256;            // 0..1023
        int r = idx >> 3, c = idx & 7;      // row, float4-chunk
        float4 v = make_float4(0.f, 0.f, 0.f, 0.f);
        if (e0 + r < e) v = ea4[(size_t)(e0 + r) * 8 + c];
        __half2 h0 = __floats2half2_rn(v.x, v.y);
        __half2 h1 = __floats2half2_rn(v.z, v.w);
        uint2 o;
        o.x = *(unsigned int*)&h0;
        o.y = *(unsigned int*)&h1;
        *(uint2*)(eaS + r * QG_LDA + c * 4) = o;
    }
    __syncthreads();

    int warp = tid >> 5;
    wmma::fragment<wmma::accumulator, 16, 16, 16, float> acc;
    wmma::fill_fragment(acc, 0.f);
    #pragma unroll
    for (int k = 0; k < 2; k++) {
        wmma::fragment<wmma::matrix_a, 16, 16, 16, __half, wmma::row_major> af;
        wmma::fragment<wmma::matrix_b, 16, 16, 16, __half, wmma::row_major> bf;
        wmma::load_matrix_sync(af, eaS + warp * 16 * QG_LDA + k * 16, QG_LDA);
        wmma::load_matrix_sync(bf, WeS + k * 16 * 16, 16);
        wmma::mma_sync(acc, af, bf, acc);
    }
    wmma::store_matrix_sync(QS + warp * 16 * 16, acc, 16, wmma::mem_row_major);
    __syncthreads();

    int r = tid >> 1, half = tid & 1;
    if (e0 + r < e) {
        const float* srcq = QS + r * 16 + half * 8;
        const float* bb   = bs + half * 8;
        __half2 h0 = __floats2half2_rn(srcq[0] + bb[0], srcq[1] + bb[1]);
        __half2 h1 = __floats2half2_rn(srcq[2] + bb[2], srcq[3] + bb[3]);
        __half2 h2 = __floats2half2_rn(srcq[4] + bb[4], srcq[5] + bb[5]);
        __half2 h3 = __floats2half2_rn(srcq[6] + bb[6], srcq[7] + bb[7]);
        uint4 o;
        o.x = *(unsigned int*)&h0;
        o.y = *(unsigned int*)&h1;
        o.z = *(unsigned int*)&h2;
        o.w = *(unsigned int*)&h3;
        *(uint4*)(g_Q + (size_t)(e0 + r) * 16 + half * 8) = o;
    }
}

// ---------------------------------------------------------------- edge output: out = logsoftmax(P_src[s] + P_dst[d] + Q[e])
#define EB 16   // edges per block (256 threads = 16 edges x 16 classes)
__global__ void k_edge3(const int* __restrict__ src, const int* __restrict__ dst,
                        float* __restrict__ out, int e) {
    int tid = threadIdx.x;
    int el = tid >> 4, c = tid & 15;
    int edge = blockIdx.x * EB + el;
    bool valid = edge < e;
    int ce = valid ? edge : e - 1;

    int s = src[ce], d = dst[ce];
    float q  = __half2float(g_Q[(size_t)ce * 16 + c]);
    float ps = __half2float(g_P[(size_t)s * 32 + c]);
    float pd = __half2float(g_P[(size_t)d * 32 + 16 + c]);
    float acc = q + ps + pd;

    float m = acc;
    #pragma unroll
    for (int off = 8; off; off >>= 1)
        m = fmaxf(m, __shfl_xor_sync(0xffffffffu, m, off));
    float ex = __expf(acc - m);
    float ss = ex;
    #pragma unroll
    for (int off = 8; off; off >>= 1)
        ss += __shfl_xor_sync(0xffffffffu, ss, off);
    float res = acc - m - __logf(ss);
    if (valid) out[(size_t)edge * CDIM + c] = res;
}

// ---------------------------------------------------------------- launch
extern "C" void kernel_launch(void* const* d_in, const int* in_sizes, int n_in,
                              void* d_out, int out_size) {
    const float* x     = (const float*)d_in[0];
    const int*   ei    = (const int*)  d_in[1];
    const float* eattr = (const float*)d_in[2];
    const float* W1 = (const float*)d_in[3];  const float* b1 = (const float*)d_in[4];
    const float* W2 = (const float*)d_in[5];  const float* b2 = (const float*)d_in[6];
    const float* W3 = (const float*)d_in[7];  const float* b3 = (const float*)d_in[8];
    const float* Wfc = (const float*)d_in[9]; const float* bfc = (const float*)d_in[10];
    float* out = (float*)d_out;

    int n = in_sizes[0] / HDIM;
    int e = in_sizes[1] / 2;
    const int* src = ei;
    const int* dst = ei + e;

    cudaFuncSetAttribute(k_gemm_wmma, cudaFuncAttributeMaxDynamicSharedMemorySize, GW_SMEM);

    // Lazily-created side stream + events (host resources; recorded graph work
    // is identical every call).
    static cudaStream_t s2 = nullptr;
    static cudaEvent_t evFork = nullptr, evJoin = nullptr;
    if (!s2) {
        cudaStreamCreateWithFlags(&s2, cudaStreamNonBlocking);
        cudaEventCreateWithFlags(&evFork, cudaEventDisableTiming);
        cudaEventCreateWithFlags(&evJoin, cudaEventDisableTiming);
    }

    int bc   = (n + 255) / 256;
    int be   = (e + 255) / 256;
    int bgem = (n + 127) / 128;
    int bagg = (int)(((long long)n * 16 + 255) / 256);   // 16 lanes per node
    int bedg = (e + EB - 1) / EB;
    int bqg  = (e + 127) / 128;

    // ---- fused prologue: W fp16 converts + cnt_zero + allocator reset
    k_prologue<<<48 + bc, 256>>>(W1, W2, W3, n);

    // ---- histogram + alloc (produce g_cnt, g_dinv, g_start/g_cursor) — main stream
    k_qgemm<<<bqg, 256>>>(eattr, Wfc, bfc, dst, e);
    k_alloc<<<bc, 256>>>(n);

    // ---- FORK: fill (writes g_csrsrc/g_cursor only) runs on s2, concurrent with
    //      gemm1 (reads x/g_Wh/g_dinv, writes g_lin) — disjoint state.
    cudaEventRecord(evFork, 0);
    cudaStreamWaitEvent(s2, evFork, 0);
    k_fill<<<be, 256, 0, s2>>>(src, dst, e);
    cudaEventRecord(evJoin, s2);

    k_gemm_wmma<<<bgem, 256, GW_SMEM>>>(x, n, 0);

    // ---- JOIN: aggregate needs both g_lin and g_csrsrc
    cudaStreamWaitEvent(0, evJoin, 0);

    k_aggregate<<<bagg, 256>>>(b1, n);

    k_gemm_wmma<<<bgem, 256, GW_SMEM>>>(nullptr, n, 1);
    k_aggregate<<<bagg, 256>>>(b2, n);

    k_gemm_wmma<<<bgem, 256, GW_SMEM>>>(nullptr, n, 2);
    k_aggregate<<<bagg, 256>>>(b3, n);

    // ---- factored edge classifier
    k_proj <<<(n + PROJ_BM - 1) / PROJ_BM, 256>>>(Wfc, n);
    k_edge3<<<bedg, 256>>>(src, dst, out, e);
}